// round 8
// baseline (speedup 1.0000x reference)
#include <cuda_runtime.h>
#include <cstdint>

// PadVariable reflect-pad gather with L2 residency partitioning.
// out[n,t,:] = x[n, reflect(t - pad0[n], lens[n]), :], zero where t >= L+p0+p1.
//
// Steady-state model (graph replay loop): x = 64MB fits in the 126MB L2 across
// replays IF the 94MB output write stream doesn't evict it. So:
//   - x loads:  ld.global.nc.L2::cache_hint with createpolicy evict_last
//               (protected L2 set -> x stays resident between replays)
//   - stores:   __stcs (evict_first -> writes stream through, never compete)
// SM-side body is the measured-best R2 config: grid=(tiles, N), 256 thr,
// f4 = tid & 15, trow = tid >> 4, UNROLL=4, 32-bit indices.

#define F4_      16   // F=64 floats -> 16 float4
#define TROWS_   16   // 256 / F4_
#define UNROLL_  4
#define TILE_T_  (TROWS_ * UNROLL_)   // 64 t per block

__device__ __forceinline__ float4 ldg_evict_last(const float4* p, uint64_t pol) {
    float4 v;
    asm volatile(
        "ld.global.nc.L2::cache_hint.v4.f32 {%0,%1,%2,%3}, [%4], %5;"
        : "=f"(v.x), "=f"(v.y), "=f"(v.z), "=f"(v.w)
        : "l"(p), "l"(pol));
    return v;
}

__global__ __launch_bounds__(256)
void pad_variable_kernel(const float4* __restrict__ x4,
                         const int* __restrict__ lens,
                         const int* __restrict__ pad,  // (2, N)
                         float4* __restrict__ out4,
                         int N, int T, int Tp) {
    const int n    = blockIdx.y;
    const int tid  = threadIdx.x;
    const int f4   = tid & (F4_ - 1);
    const int trow = tid >> 4;
    const int t0   = blockIdx.x * TILE_T_ + trow;

    // L2 policy: keep x lines in the evict-last (protected) set.
    uint64_t pol;
    asm("createpolicy.fractional.L2::evict_last.b64 %0, 1.0;" : "=l"(pol));

    const int L  = __ldg(&lens[n]);
    const int p0 = __ldg(&pad[n]);
    const int p1 = __ldg(&pad[N + n]);
    const int vlim = L + p0 + p1;

    // 32-bit element offsets (max ~6.3M float4 < 2^31) — safe here.
    const float4* __restrict__ xrow = x4 + (unsigned)(n * T * F4_);
    float4* __restrict__ orow       = out4 + (unsigned)(n * Tp * F4_);

    int t[UNROLL_];
    int idx[UNROLL_];
    bool store_ok[UNROLL_];
    bool load_ok[UNROLL_];

    #pragma unroll
    for (int u = 0; u < UNROLL_; u++) {
        t[u] = t0 + u * TROWS_;
        store_ok[u] = t[u] < Tp;
        int rel = t[u] - p0;
        int s = (rel < 0) ? -rel : ((rel < L) ? rel : (2 * L - rel - 2));
        s = min(max(s, 0), T - 1);
        idx[u] = s * F4_ + f4;
        load_ok[u] = store_ok[u] && (t[u] < vlim);
    }

    // Front-batched independent loads (MLP = 4), evict_last protected.
    float4 v[UNROLL_];
    #pragma unroll
    for (int u = 0; u < UNROLL_; u++) {
        if (load_ok[u])
            v[u] = ldg_evict_last(&xrow[(unsigned)idx[u]], pol);
        else
            v[u] = make_float4(0.f, 0.f, 0.f, 0.f);
    }

    // Evict-first streaming stores: never evict protected x lines.
    #pragma unroll
    for (int u = 0; u < UNROLL_; u++) {
        if (store_ok[u])
            __stcs(&orow[(unsigned)(t[u] * F4_ + f4)], v[u]);
    }
}

extern "C" void kernel_launch(void* const* d_in, const int* in_sizes, int n_in,
                              void* d_out, int out_size) {
    const float* x    = (const float*)d_in[0];  // (N, T, F) float32
    const int*   lens = (const int*)d_in[1];    // (N,)
    const int*   pad  = (const int*)d_in[2];    // (2, N)

    float* out = (float*)d_out;

    const int N = in_sizes[1];           // 64
    const int F = 64;                    // feature dim (16 float4)
    const int T = in_sizes[0] / (N * F); // 4096
    const int Tp = out_size / (N * F);

    dim3 grid((Tp + TILE_T_ - 1) / TILE_T_, N);
    pad_variable_kernel<<<grid, 256>>>(
        (const float4*)x, lens, pad, (float4*)out, N, T, Tp);
}

// round 9
// speedup vs baseline: 1.0760x; 1.0760x over previous
#include <cuda_runtime.h>
#include <cstdint>

// PadVariable reflect-pad gather — 256-bit (v8.f32) load/store version.
// out[n,t,:] = x[n, reflect(t - pad0[n], lens[n]), :], zero where t >= L+p0+p1.
// sm_103a supports 256-bit global accesses: each thread moves 32B per row.
// 256 threads: f8 = tid & 7 (8 threads x 32B = 256B row), trow = tid >> 3
// (32 rows), UNROLL=2 -> TILE_T=64 t per block. Streaming (.cs) stores.

#define F8_      8    // 64 floats per row -> 8 x 32B chunks
#define TROWS_   32   // 256 / F8_
#define UNROLL_  2
#define TILE_T_  (TROWS_ * UNROLL_)   // 64 t per block

struct __align__(32) f8vec { float v[8]; };

__device__ __forceinline__ f8vec ldg256(const float* p) {
    f8vec r;
    asm volatile(
        "ld.global.nc.v8.f32 {%0,%1,%2,%3,%4,%5,%6,%7}, [%8];"
        : "=f"(r.v[0]), "=f"(r.v[1]), "=f"(r.v[2]), "=f"(r.v[3]),
          "=f"(r.v[4]), "=f"(r.v[5]), "=f"(r.v[6]), "=f"(r.v[7])
        : "l"(p));
    return r;
}

__device__ __forceinline__ void stg256_cs(float* p, const f8vec& r) {
    asm volatile(
        "st.global.cs.v8.f32 [%0], {%1,%2,%3,%4,%5,%6,%7,%8};"
        :: "l"(p),
           "f"(r.v[0]), "f"(r.v[1]), "f"(r.v[2]), "f"(r.v[3]),
           "f"(r.v[4]), "f"(r.v[5]), "f"(r.v[6]), "f"(r.v[7])
        : "memory");
}

__global__ __launch_bounds__(256)
void pad_variable_kernel(const float* __restrict__ x,
                         const int* __restrict__ lens,
                         const int* __restrict__ pad,  // (2, N)
                         float* __restrict__ out,
                         int N, int T, int Tp) {
    const int n    = blockIdx.y;
    const int tid  = threadIdx.x;
    const int f8   = tid & (F8_ - 1);      // which 32B chunk of the row
    const int trow = tid >> 3;
    const int t0   = blockIdx.x * TILE_T_ + trow;

    const int L  = __ldg(&lens[n]);
    const int p0 = __ldg(&pad[n]);
    const int p1 = __ldg(&pad[N + n]);
    const int vlim = L + p0 + p1;

    // 32-bit element offsets (max ~25M floats < 2^31 bytes) — safe here.
    const float* __restrict__ xrow = x + (unsigned)(n * T * 64);
    float* __restrict__ orow       = out + (unsigned)(n * Tp * 64);
    const int foff = f8 * 8;  // float offset of this thread's 32B chunk

    int t[UNROLL_];
    int src[UNROLL_];
    bool store_ok[UNROLL_];
    bool load_ok[UNROLL_];

    #pragma unroll
    for (int u = 0; u < UNROLL_; u++) {
        t[u] = t0 + u * TROWS_;
        store_ok[u] = t[u] < Tp;
        int rel = t[u] - p0;
        int s = (rel < 0) ? -rel : ((rel < L) ? rel : (2 * L - rel - 2));
        src[u] = min(max(s, 0), T - 1);
        load_ok[u] = store_ok[u] && (t[u] < vlim);
    }

    // Front-batched independent 256-bit loads.
    f8vec v[UNROLL_];
    #pragma unroll
    for (int u = 0; u < UNROLL_; u++) {
        if (load_ok[u]) {
            v[u] = ldg256(&xrow[(unsigned)(src[u] * 64 + foff)]);
        } else {
            #pragma unroll
            for (int k = 0; k < 8; k++) v[u].v[k] = 0.f;
        }
    }

    // Streaming 256-bit stores.
    #pragma unroll
    for (int u = 0; u < UNROLL_; u++) {
        if (store_ok[u])
            stg256_cs(&orow[(unsigned)(t[u] * 64 + foff)], v[u]);
    }
}

extern "C" void kernel_launch(void* const* d_in, const int* in_sizes, int n_in,
                              void* d_out, int out_size) {
    const float* x    = (const float*)d_in[0];  // (N, T, F) float32
    const int*   lens = (const int*)d_in[1];    // (N,)
    const int*   pad  = (const int*)d_in[2];    // (2, N)

    float* out = (float*)d_out;

    const int N = in_sizes[1];           // 64
    const int F = 64;                    // feature dim
    const int T = in_sizes[0] / (N * F); // 4096
    const int Tp = out_size / (N * F);

    dim3 grid((Tp + TILE_T_ - 1) / TILE_T_, N);
    pad_variable_kernel<<<grid, 256>>>(
        x, lens, pad, out, N, T, Tp);
}